// round 2
// baseline (speedup 1.0000x reference)
#include <cuda_runtime.h>

#define N_MAX   100000
#define FIN     512
#define HID     16
#define NC      7
#define H2      8
#define NB      512            // nodes per block in gemm1
#define KC      16             // k-chunk staged in smem

// -------- scratch --------
__device__ float g_dinv[N_MAX];
__device__ float g_deg [N_MAX];
__device__ float g_xs  [N_MAX * HID];   // dinv * (x @ W1)
__device__ float g_agg1[N_MAX * HID];
__device__ float g_hs  [N_MAX * H2];    // dinv * (relu(h1) @ W2)
__device__ float g_agg2[N_MAX * H2];

__device__ __forceinline__ void red_add_v4(float* p, float4 v) {
    asm volatile("red.global.add.v4.f32 [%0], {%1,%2,%3,%4};"
                 :: "l"(p), "f"(v.x), "f"(v.y), "f"(v.z), "f"(v.w)
                 : "memory");
}
__device__ __forceinline__ unsigned long long pack2(float a, float b) {
    unsigned long long r;
    asm("mov.b64 %0,{%1,%2};" : "=l"(r) : "f"(a), "f"(b));
    return r;
}
__device__ __forceinline__ void ffma2(unsigned long long& d,
                                      unsigned long long a, unsigned long long b) {
    asm("fma.rn.f32x2 %0,%1,%2,%0;" : "+l"(d) : "l"(a), "l"(b));
}
__device__ __forceinline__ float2 unpack2(unsigned long long v) {
    float2 u;
    asm("mov.b64 {%0,%1},%2;" : "=f"(u.x), "=f"(u.y) : "l"(v));
    return u;
}

// -------- init --------
__global__ void k_init(int n) {
    int stride = gridDim.x * blockDim.x;
    int t0 = blockIdx.x * blockDim.x + threadIdx.x;
    for (int t = t0; t < n * HID; t += stride) g_agg1[t] = 0.f;
    for (int t = t0; t < n * H2;  t += stride) g_agg2[t] = 0.f;
    for (int t = t0; t < n;       t += stride) g_deg[t]  = 1.f;
}

__global__ void k_deg(const int* __restrict__ col, int ne) {
    int e = blockIdx.x * blockDim.x + threadIdx.x;
    if (e < ne) atomicAdd(&g_deg[col[e]], 1.0f);
}

__global__ void k_dinv(int n) {
    int i = blockIdx.x * blockDim.x + threadIdx.x;
    if (i < n) g_dinv[i] = rsqrtf(g_deg[i]);
}

// -------- xs = dinv * (x @ W1), f32x2 packed FMAs, smem-staged x --------
__global__ void __launch_bounds__(256)
k_gemm1(const float* __restrict__ x, const float* __restrict__ W1, int n) {
    __shared__ float sX[NB * (KC + 1)];   // stride 17, conflict-free
    const int tid  = threadIdx.x;
    const int base = blockIdx.x * NB;

    unsigned long long acc0[HID / 2], acc1[HID / 2];
#pragma unroll
    for (int p = 0; p < HID / 2; p++) { acc0[p] = 0ull; acc1[p] = 0ull; }

    const ulonglong2* __restrict__ Wv = (const ulonglong2*)W1;

    for (int kc = 0; kc < FIN; kc += KC) {
        __syncthreads();
        // stage x[base..base+511][kc..kc+KC) : 512 rows x 16 floats = 2048 float4
#pragma unroll
        for (int i = 0; i < 8; i++) {
            int t  = tid + i * 256;      // 0..2047
            int r  = t >> 2;             // row 0..511
            int c4 = t & 3;              // float4 col 0..3
            int gn = base + r;
            float4 v = make_float4(0.f, 0.f, 0.f, 0.f);
            if (gn < n)
                v = __ldg((const float4*)(x + (size_t)gn * FIN + kc) + c4);
            float* s = &sX[r * (KC + 1) + c4 * 4];
            s[0] = v.x; s[1] = v.y; s[2] = v.z; s[3] = v.w;
        }
        __syncthreads();

        const float* xr0 = &sX[tid * (KC + 1)];
        const float* xr1 = &sX[(tid + 256) * (KC + 1)];
#pragma unroll
        for (int k = 0; k < KC; k++) {
            unsigned long long xx0 = pack2(xr0[k], xr0[k]);
            unsigned long long xx1 = pack2(xr1[k], xr1[k]);
            const ulonglong2* wr = &Wv[(kc + k) * (HID / 4)];
#pragma unroll
            for (int p = 0; p < HID / 4; p++) {
                ulonglong2 w = __ldg(&wr[p]);
                ffma2(acc0[2 * p],     w.x, xx0);
                ffma2(acc0[2 * p + 1], w.y, xx0);
                ffma2(acc1[2 * p],     w.x, xx1);
                ffma2(acc1[2 * p + 1], w.y, xx1);
            }
        }
    }

    int n0 = base + tid, n1 = base + tid + 256;
    if (n0 < n) {
        float d = g_dinv[n0];
        float4* o = (float4*)(&g_xs[(size_t)n0 * HID]);
#pragma unroll
        for (int p = 0; p < HID / 4; p++) {
            float2 a = unpack2(acc0[2 * p]), b = unpack2(acc0[2 * p + 1]);
            o[p] = make_float4(d * a.x, d * a.y, d * b.x, d * b.y);
        }
    }
    if (n1 < n) {
        float d = g_dinv[n1];
        float4* o = (float4*)(&g_xs[(size_t)n1 * HID]);
#pragma unroll
        for (int p = 0; p < HID / 4; p++) {
            float2 a = unpack2(acc1[2 * p]), b = unpack2(acc1[2 * p + 1]);
            o[p] = make_float4(d * a.x, d * a.y, d * b.x, d * b.y);
        }
    }
}

// -------- layer-1 edge aggregation: pure gather + red (norm folded) --------
__global__ void k_agg1(const int* __restrict__ row,
                       const int* __restrict__ col, int ne) {
    int t = blockIdx.x * blockDim.x + threadIdx.x;
    int e = t >> 2, q = t & 3;
    if (e >= ne) return;
    int r = __ldg(&row[e]);
    int c = __ldg(&col[e]);
    float4 v = *(const float4*)(&g_xs[(size_t)r * HID + q * 4]);
    red_add_v4(&g_agg1[(size_t)c * HID + q * 4], v);
}

// -------- h1 = relu(dinv*(agg1 + xs) + b1); hs = dinv * (h1 @ W2) --------
__global__ void k_h1(const float* __restrict__ b1,
                     const float* __restrict__ W2, int n) {
    __shared__ float sW2[HID * NC];
    __shared__ float sb1[HID];
    if (threadIdx.x < HID * NC) sW2[threadIdx.x] = W2[threadIdx.x];
    if (threadIdx.x < HID)      sb1[threadIdx.x] = b1[threadIdx.x];
    __syncthreads();

    int i = blockIdx.x * blockDim.x + threadIdx.x;
    if (i >= n) return;

    float d = g_dinv[i];
    float h[HID];
#pragma unroll
    for (int j = 0; j < HID; j++) {
        float v = d * (g_agg1[(size_t)i * HID + j] + g_xs[(size_t)i * HID + j]) + sb1[j];
        h[j] = v > 0.f ? v : 0.f;
    }
    float y[H2];
#pragma unroll
    for (int j = 0; j < H2; j++) y[j] = 0.f;
#pragma unroll
    for (int k = 0; k < HID; k++) {
        float hk = h[k];
#pragma unroll
        for (int j = 0; j < NC; j++) y[j] += hk * sW2[k * NC + j];
    }
    float4* o = (float4*)(&g_hs[(size_t)i * H2]);
    o[0] = make_float4(d * y[0], d * y[1], d * y[2], d * y[3]);
    o[1] = make_float4(d * y[4], d * y[5], d * y[6], 0.f);
}

// -------- layer-2 edge aggregation --------
__global__ void k_agg2(const int* __restrict__ row,
                       const int* __restrict__ col, int ne) {
    int t = blockIdx.x * blockDim.x + threadIdx.x;
    int e = t >> 1, q = t & 1;
    if (e >= ne) return;
    int r = __ldg(&row[e]);
    int c = __ldg(&col[e]);
    float4 v = *(const float4*)(&g_hs[(size_t)r * H2 + q * 4]);
    red_add_v4(&g_agg2[(size_t)c * H2 + q * 4], v);
}

// -------- out = dinv*(agg2 + hs) + b2 --------
__global__ void k_out(float* __restrict__ out, const float* __restrict__ b2, int n) {
    int i = blockIdx.x * blockDim.x + threadIdx.x;
    if (i >= n) return;
    float d = g_dinv[i];
#pragma unroll
    for (int j = 0; j < NC; j++)
        out[(size_t)i * NC + j] =
            d * (g_agg2[(size_t)i * H2 + j] + g_hs[(size_t)i * H2 + j]) + __ldg(&b2[j]);
}

extern "C" void kernel_launch(void* const* d_in, const int* in_sizes, int n_in,
                              void* d_out, int out_size) {
    const float* x  = (const float*)d_in[0];
    const int*   ei = (const int*)  d_in[1];
    const float* W1 = (const float*)d_in[2];
    const float* b1 = (const float*)d_in[3];
    const float* W2 = (const float*)d_in[4];
    const float* b2 = (const float*)d_in[5];

    int n  = in_sizes[0] / FIN;
    int ne = in_sizes[1] / 2;
    const int* row = ei;
    const int* col = ei + ne;

    k_init <<<148 * 8, 256>>>(n);
    k_deg  <<<(ne + 255) / 256, 256>>>(col, ne);
    k_dinv <<<(n + 255) / 256, 256>>>(n);
    k_gemm1<<<(n + NB - 1) / NB, 256>>>(x, W1, n);
    k_agg1 <<<((ne * 4) + 255) / 256, 256>>>(row, col, ne);
    k_h1   <<<(n + 255) / 256, 256>>>(b1, W2, n);
    k_agg2 <<<((ne * 2) + 255) / 256, 256>>>(row, col, ne);
    k_out  <<<(n + 255) / 256, 256>>>((float*)d_out, b2, n);
}

// round 3
// speedup vs baseline: 1.4852x; 1.4852x over previous
#include <cuda_runtime.h>

#define N_MAX   100000
#define FIN     512
#define HID     16
#define NC      7
#define H2      8
#define NB      256            // nodes per block in gemm1
#define TPB     128            // threads per block in gemm1
#define KC      16             // k-chunk staged in smem
#define NCHUNK  (FIN / KC)     // 32

// -------- scratch --------
__device__ float g_dinv[N_MAX];
__device__ float g_deg [N_MAX];
__device__ float g_xs  [N_MAX * HID];   // dinv * (x @ W1)
__device__ float g_agg1[N_MAX * HID];
__device__ float g_hs  [N_MAX * H2];    // dinv * (relu(h1) @ W2)
__device__ float g_agg2[N_MAX * H2];

__device__ __forceinline__ void red_add_v4(float* p, float4 v) {
    asm volatile("red.global.add.v4.f32 [%0], {%1,%2,%3,%4};"
                 :: "l"(p), "f"(v.x), "f"(v.y), "f"(v.z), "f"(v.w)
                 : "memory");
}
__device__ __forceinline__ unsigned long long pack2(float a, float b) {
    unsigned long long r;
    asm("mov.b64 %0,{%1,%2};" : "=l"(r) : "f"(a), "f"(b));
    return r;
}
__device__ __forceinline__ void ffma2(unsigned long long& d,
                                      unsigned long long a, unsigned long long b) {
    asm("fma.rn.f32x2 %0,%1,%2,%0;" : "+l"(d) : "l"(a), "l"(b));
}
__device__ __forceinline__ float2 unpack2(unsigned long long v) {
    float2 u;
    asm("mov.b64 {%0,%1},%2;" : "=f"(u.x), "=f"(u.y) : "l"(v));
    return u;
}

// -------- init --------
__global__ void k_init(int n) {
    int stride = gridDim.x * blockDim.x;
    int t0 = blockIdx.x * blockDim.x + threadIdx.x;
    for (int t = t0; t < n * HID; t += stride) g_agg1[t] = 0.f;
    for (int t = t0; t < n * H2;  t += stride) g_agg2[t] = 0.f;
    for (int t = t0; t < n;       t += stride) g_deg[t]  = 1.f;
}

__global__ void k_deg(const int* __restrict__ col, int ne) {
    int e = blockIdx.x * blockDim.x + threadIdx.x;
    if (e < ne) atomicAdd(&g_deg[col[e]], 1.0f);
}

__global__ void k_dinv(int n) {
    int i = blockIdx.x * blockDim.x + threadIdx.x;
    if (i < n) g_dinv[i] = rsqrtf(g_deg[i]);
}

// -------- xs = dinv * (x @ W1): 2 nodes/thread, reg-prefetch double buffer ----
__global__ void __launch_bounds__(TPB)
k_gemm1(const float* __restrict__ x, const float* __restrict__ W1, int n) {
    __shared__ float sX[NB * (KC + 1)];   // 17408 B, stride 17 (odd => no conflicts)
    __shared__ float sW[KC * HID];        // 1024 B
    const int tid  = threadIdx.x;
    const int base = blockIdx.x * NB;

    unsigned long long acc0[HID / 2], acc1[HID / 2];
#pragma unroll
    for (int p = 0; p < HID / 2; p++) { acc0[p] = 0ull; acc1[p] = 0ull; }

    // staging map: t = tid + i*TPB in [0,1024): row r = t>>2 (256 rows),
    // float4 col c4 = t&3 (KC=16 floats = 4 float4 per row)
    const int sr  = tid >> 2;         // base row for this thread's stages
    const int sc4 = tid & 3;

    float4 px[8];
    float4 pw;          // W chunk: 16x16 floats = 64 float4, threads 0..63
    // ---- prefetch chunk 0 ----
#pragma unroll
    for (int i = 0; i < 8; i++) {
        int r  = sr + i * (TPB / 4);
        int gn = base + r;
        px[i] = (gn < n) ? __ldg((const float4*)(x + (size_t)gn * FIN) + sc4)
                         : make_float4(0.f, 0.f, 0.f, 0.f);
    }
    if (tid < KC * HID / 4) pw = __ldg((const float4*)W1 + tid);

    for (int c = 0; c < NCHUNK; c++) {
        __syncthreads();   // compute of previous chunk done
        // ---- store prefetched data to smem ----
#pragma unroll
        for (int i = 0; i < 8; i++) {
            float* s = &sX[(sr + i * (TPB / 4)) * (KC + 1) + sc4 * 4];
            s[0] = px[i].x; s[1] = px[i].y; s[2] = px[i].z; s[3] = px[i].w;
        }
        if (tid < KC * HID / 4) ((float4*)sW)[tid] = pw;
        __syncthreads();

        // ---- prefetch next chunk (latency hides under compute below) ----
        if (c + 1 < NCHUNK) {
            int kc = (c + 1) * KC;
#pragma unroll
            for (int i = 0; i < 8; i++) {
                int r  = sr + i * (TPB / 4);
                int gn = base + r;
                px[i] = (gn < n)
                      ? __ldg((const float4*)(x + (size_t)gn * FIN + kc) + sc4)
                      : make_float4(0.f, 0.f, 0.f, 0.f);
            }
            if (tid < KC * HID / 4)
                pw = __ldg((const float4*)(W1 + kc * HID) + tid);
        }

        // ---- compute: nodes tid and tid+128 (lane stride 17 words) ----
        const float* xr0 = &sX[tid * (KC + 1)];
        const float* xr1 = &sX[(tid + TPB) * (KC + 1)];
#pragma unroll
        for (int k = 0; k < KC; k++) {
            unsigned long long xx0 = pack2(xr0[k], xr0[k]);
            unsigned long long xx1 = pack2(xr1[k], xr1[k]);
            const ulonglong2* wr = (const ulonglong2*)(&sW[k * HID]);
#pragma unroll
            for (int p = 0; p < HID / 4; p++) {
                ulonglong2 w = wr[p];
                ffma2(acc0[2 * p],     w.x, xx0);
                ffma2(acc0[2 * p + 1], w.y, xx0);
                ffma2(acc1[2 * p],     w.x, xx1);
                ffma2(acc1[2 * p + 1], w.y, xx1);
            }
        }
    }

    int n0 = base + tid, n1 = base + TPB + tid;
    if (n0 < n) {
        float d = g_dinv[n0];
        float4* o = (float4*)(&g_xs[(size_t)n0 * HID]);
#pragma unroll
        for (int p = 0; p < HID / 4; p++) {
            float2 a = unpack2(acc0[2 * p]), b = unpack2(acc0[2 * p + 1]);
            o[p] = make_float4(d * a.x, d * a.y, d * b.x, d * b.y);
        }
    }
    if (n1 < n) {
        float d = g_dinv[n1];
        float4* o = (float4*)(&g_xs[(size_t)n1 * HID]);
#pragma unroll
        for (int p = 0; p < HID / 4; p++) {
            float2 a = unpack2(acc1[2 * p]), b = unpack2(acc1[2 * p + 1]);
            o[p] = make_float4(d * a.x, d * a.y, d * b.x, d * b.y);
        }
    }
}

// -------- layer-1 edge aggregation: pure gather + red (norm folded) --------
__global__ void k_agg1(const int* __restrict__ row,
                       const int* __restrict__ col, int ne) {
    int t = blockIdx.x * blockDim.x + threadIdx.x;
    int e = t >> 2, q = t & 3;
    if (e >= ne) return;
    int r = __ldg(&row[e]);
    int c = __ldg(&col[e]);
    float4 v = *(const float4*)(&g_xs[(size_t)r * HID + q * 4]);
    red_add_v4(&g_agg1[(size_t)c * HID + q * 4], v);
}

// -------- h1 = relu(dinv*(agg1 + xs) + b1); hs = dinv * (h1 @ W2) --------
__global__ void k_h1(const float* __restrict__ b1,
                     const float* __restrict__ W2, int n) {
    __shared__ float sW2[HID * NC];
    __shared__ float sb1[HID];
    if (threadIdx.x < HID * NC) sW2[threadIdx.x] = W2[threadIdx.x];
    if (threadIdx.x < HID)      sb1[threadIdx.x] = b1[threadIdx.x];
    __syncthreads();

    int i = blockIdx.x * blockDim.x + threadIdx.x;
    if (i >= n) return;

    float d = g_dinv[i];
    float h[HID];
#pragma unroll
    for (int j = 0; j < HID; j++) {
        float v = d * (g_agg1[(size_t)i * HID + j] + g_xs[(size_t)i * HID + j]) + sb1[j];
        h[j] = v > 0.f ? v : 0.f;
    }
    float y[H2];
#pragma unroll
    for (int j = 0; j < H2; j++) y[j] = 0.f;
#pragma unroll
    for (int k = 0; k < HID; k++) {
        float hk = h[k];
#pragma unroll
        for (int j = 0; j < NC; j++) y[j] += hk * sW2[k * NC + j];
    }
    float4* o = (float4*)(&g_hs[(size_t)i * H2]);
    o[0] = make_float4(d * y[0], d * y[1], d * y[2], d * y[3]);
    o[1] = make_float4(d * y[4], d * y[5], d * y[6], 0.f);
}

// -------- layer-2 edge aggregation --------
__global__ void k_agg2(const int* __restrict__ row,
                       const int* __restrict__ col, int ne) {
    int t = blockIdx.x * blockDim.x + threadIdx.x;
    int e = t >> 1, q = t & 1;
    if (e >= ne) return;
    int r = __ldg(&row[e]);
    int c = __ldg(&col[e]);
    float4 v = *(const float4*)(&g_hs[(size_t)r * H2 + q * 4]);
    red_add_v4(&g_agg2[(size_t)c * H2 + q * 4], v);
}

// -------- out = dinv*(agg2 + hs) + b2 --------
__global__ void k_out(float* __restrict__ out, const float* __restrict__ b2, int n) {
    int i = blockIdx.x * blockDim.x + threadIdx.x;
    if (i >= n) return;
    float d = g_dinv[i];
#pragma unroll
    for (int j = 0; j < NC; j++)
        out[(size_t)i * NC + j] =
            d * (g_agg2[(size_t)i * H2 + j] + g_hs[(size_t)i * H2 + j]) + __ldg(&b2[j]);
}

extern "C" void kernel_launch(void* const* d_in, const int* in_sizes, int n_in,
                              void* d_out, int out_size) {
    const float* x  = (const float*)d_in[0];
    const int*   ei = (const int*)  d_in[1];
    const float* W1 = (const float*)d_in[2];
    const float* b1 = (const float*)d_in[3];
    const float* W2 = (const float*)d_in[4];
    const float* b2 = (const float*)d_in[5];

    int n  = in_sizes[0] / FIN;
    int ne = in_sizes[1] / 2;
    const int* row = ei;
    const int* col = ei + ne;

    k_init <<<148 * 8, 256>>>(n);
    k_deg  <<<(ne + 255) / 256, 256>>>(col, ne);
    k_dinv <<<(n + 255) / 256, 256>>>(n);
    k_gemm1<<<(n + NB - 1) / NB, TPB>>>(x, W1, n);
    k_agg1 <<<((ne * 4) + 255) / 256, 256>>>(row, col, ne);
    k_h1   <<<(n + 255) / 256, 256>>>(b1, W2, n);
    k_agg2 <<<((ne * 2) + 255) / 256, 256>>>(row, col, ne);
    k_out  <<<(n + 255) / 256, 256>>>((float*)d_out, b2, n);
}